// round 16
// baseline (speedup 1.0000x reference)
#include <cuda_runtime.h>
#include <cuda_bf16.h>
#include <math.h>
#include <stdint.h>

#define NN 50000
#define EE 400000
#define E2 (EE + NN)
#define OUTD 16
#define MTILES 391  // ceil(50000/128)

// ---------------- scratch (device globals; no allocs allowed) ----------------
__device__ __align__(16) float g_xl1[NN * 256];
__device__ __align__(16) float g_xr1[NN * 256];
__device__ __align__(16) float g_xl2[NN * OUTD];
__device__ __align__(16) float g_xr2[NN * OUTD];
__device__ int g_esrc[E2];
__device__ int g_counts[NN];   // zero-initialized; re-zeroed by k_scan1 each call
__device__ int g_fill[NN];     // zero-initialized; re-zeroed by k_scan1 each call
__device__ int g_rowptr[NN + 1];  // block-local exclusive scans; +g_boff at use
__device__ int g_bsum[64];
__device__ int g_boff[64];
__device__ int g_scanctr;      // zero-init; self-resetting
__device__ __align__(16) float g_bcat1[512];
__device__ __align__(16) float g_bcat2[32];
// bf16 hi/lo split operands for tensor-core GEMMs
__device__ __align__(16) __nv_bfloat16 g_Ahi[NN * 256];
__device__ __align__(16) __nv_bfloat16 g_Alo[NN * 256];
__device__ __align__(16) __nv_bfloat16 g_Bhi[512 * 256];
__device__ __align__(16) __nv_bfloat16 g_Blo[512 * 256];
__device__ __align__(16) __nv_bfloat16 g_h1hi[NN * 256];
__device__ __align__(16) __nv_bfloat16 g_h1lo[NN * 256];
__device__ __align__(16) __nv_bfloat16 g_W2hi[32 * 256];
__device__ __align__(16) __nv_bfloat16 g_W2lo[32 * 256];

__device__ __forceinline__ float lrelu(float v) { return v > 0.f ? v : 0.2f * v; }

// row range for dst node d (block-local rowptr + block offset)
__device__ __forceinline__ void row_range(int d, int& p0, int& p1) {
    p0 = g_rowptr[d] + g_boff[d >> 10];
    int e = d + 1;
    p1 = g_rowptr[e] + ((e < NN) ? g_boff[e >> 10] : 0);
}

// ---------------- PTX helpers (arch-portable: ldmatrix + mma.sync) ----------------
__device__ __forceinline__ uint32_t smem_u32(const void* p) {
    uint32_t a;
    asm("{ .reg .u64 t; cvta.to.shared.u64 t, %1; cvt.u32.u64 %0, t; }"
        : "=r"(a) : "l"(p));
    return a;
}
__device__ __forceinline__ void cpa16(uint32_t dst, const void* src) {
    asm volatile("cp.async.cg.shared.global [%0], [%1], 16;" ::"r"(dst), "l"(src)
                 : "memory");
}
template <int N>
__device__ __forceinline__ void cpwait() {
    asm volatile("cp.async.wait_group %0;" ::"n"(N) : "memory");
}
__device__ __forceinline__ void ldm4(uint32_t* r, uint32_t addr) {
    asm volatile("ldmatrix.sync.aligned.m8n8.x4.shared.b16 {%0,%1,%2,%3}, [%4];"
                 : "=r"(r[0]), "=r"(r[1]), "=r"(r[2]), "=r"(r[3])
                 : "r"(addr));
}
__device__ __forceinline__ void mma16816(float* c, const uint32_t* a, uint32_t b0,
                                         uint32_t b1) {
    asm volatile(
        "mma.sync.aligned.m16n8k16.row.col.f32.bf16.bf16.f32 "
        "{%0,%1,%2,%3}, {%4,%5,%6,%7}, {%8,%9}, {%0,%1,%2,%3};"
        : "+f"(c[0]), "+f"(c[1]), "+f"(c[2]), "+f"(c[3])
        : "r"(a[0]), "r"(a[1]), "r"(a[2]), "r"(a[3]), "r"(b0), "r"(b1));
}

// ---------------- fused init: conv_x + conv_w + prep(W2/biases) + hist ----------------
__global__ void k_init(const float* __restrict__ X,
                       const int* __restrict__ ei,
                       const float* __restrict__ Wl1, const float* __restrict__ Wr1,
                       const float* __restrict__ bl1, const float* __restrict__ br1,
                       const float* __restrict__ Wl2, const float* __restrict__ bl2,
                       const float* __restrict__ Wr2, const float* __restrict__ br2) {
    int i = blockIdx.x * blockDim.x + threadIdx.x;
    if (i < NN * 64) {
        float4 v = ((const float4*)X)[i];
        __nv_bfloat16 h0 = __float2bfloat16(v.x);
        __nv_bfloat16 h1 = __float2bfloat16(v.y);
        __nv_bfloat16 h2 = __float2bfloat16(v.z);
        __nv_bfloat16 h3 = __float2bfloat16(v.w);
        __nv_bfloat16 l0 = __float2bfloat16(v.x - __bfloat162float(h0));
        __nv_bfloat16 l1 = __float2bfloat16(v.y - __bfloat162float(h1));
        __nv_bfloat16 l2 = __float2bfloat16(v.z - __bfloat162float(h2));
        __nv_bfloat16 l3 = __float2bfloat16(v.w - __bfloat162float(h3));
        *(__nv_bfloat162*)(g_Ahi + (size_t)i * 4)     = __halves2bfloat162(h0, h1);
        *(__nv_bfloat162*)(g_Ahi + (size_t)i * 4 + 2) = __halves2bfloat162(h2, h3);
        *(__nv_bfloat162*)(g_Alo + (size_t)i * 4)     = __halves2bfloat162(l0, l1);
        *(__nv_bfloat162*)(g_Alo + (size_t)i * 4 + 2) = __halves2bfloat162(l2, l3);
    }
    if (i < 512 * 256) {
        int n = i >> 8, k = i & 255;
        float v = (n < 256) ? Wl1[k * 256 + n] : Wr1[k * 256 + (n - 256)];
        __nv_bfloat16 h = __float2bfloat16(v);
        g_Bhi[n * 256 + k] = h;
        g_Blo[n * 256 + k] = __float2bfloat16(v - __bfloat162float(h));
    }
    if (i < 32 * 256) {
        int n = i >> 8, k = i & 255;
        float v = (n < 16) ? Wl2[k * 16 + n] : Wr2[k * 16 + (n - 16)];
        __nv_bfloat16 h = __float2bfloat16(v);
        g_W2hi[n * 256 + k] = h;
        g_W2lo[n * 256 + k] = __float2bfloat16(v - __bfloat162float(h));
    }
    if (i < 512) g_bcat1[i] = (i < 256) ? bl1[i] : br1[i - 256];
    if (i < 32) g_bcat2[i] = (i < 16) ? bl2[i] : br2[i - 16];
    if (i < E2) {
        int dd = (i < EE) ? ei[EE + i] : (i - EE);
        atomicAdd(&g_counts[dd], 1);
    }
}

#define SCAN_BLOCKS 49

// scan1 + fused scan2 (last-block-done) + counter re-zeroing for next replay.
// Leaves g_rowptr block-local; consumers add g_boff[d>>10].
__global__ void k_scan1() {
    __shared__ int wsum[32];
    int tid = threadIdx.x;
    int lane = tid & 31, w = tid >> 5;
    int i = blockIdx.x * 1024 + tid;
    int v = (i < NN) ? g_counts[i] : 0;
    int x = v;
#pragma unroll
    for (int st = 1; st < 32; st <<= 1) {
        int y = __shfl_up_sync(0xffffffffu, x, st);
        if (lane >= st) x += y;
    }
    if (lane == 31) wsum[w] = x;
    __syncthreads();
    if (w == 0) {
        int s = wsum[lane];
#pragma unroll
        for (int st = 1; st < 32; st <<= 1) {
            int y = __shfl_up_sync(0xffffffffu, s, st);
            if (lane >= st) s += y;
        }
        wsum[lane] = s;
    }
    __syncthreads();
    int off = (w > 0) ? wsum[w - 1] : 0;
    int incl = x + off;
    if (i < NN) {
        g_rowptr[i] = incl - v;
        g_counts[i] = 0;
        g_fill[i] = 0;
    }
    if (tid == 1023) g_bsum[blockIdx.x] = incl;
    __syncthreads();
    if (tid == 0) {
        __threadfence();
        int prev = atomicAdd(&g_scanctr, 1);
        if (prev == SCAN_BLOCKS - 1) {
            g_scanctr = 0;
            __threadfence();
            int acc = 0;
            for (int b = 0; b < SCAN_BLOCKS; b++) { g_boff[b] = acc; acc += g_bsum[b]; }
            g_rowptr[NN] = acc;  // grand total (consumers add 0 for d+1==NN)
        }
    }
}

__global__ void k_scatter(const int* __restrict__ ei) {
    int i = blockIdx.x * blockDim.x + threadIdx.x;
    if (i >= E2) return;
    int s  = (i < EE) ? ei[i]      : (i - EE);
    int dd = (i < EE) ? ei[EE + i] : (i - EE);
    int pos = g_rowptr[dd] + g_boff[dd >> 10] + atomicAdd(&g_fill[dd], 1);
    g_esrc[pos] = s;
}

// ---------------- GEMM1 (mma.sync bf16 hi/lo): 3 accumulating passes ----------------
// block tile 128x128, warp tile 64x32 (2x4 warp grid), BK=64, 12 chunks.
// 3-stage cp.async pipeline; manual ks-pipelined fragment double-buffering.
// (R12 configuration — proven best: 2 CTAs/SM.)
#define KS 72             // bf16 elems per smem row (144B: 16B-aligned, conflict-free)
#define HALFSTAGE 18432   // 128*72*2 bytes (one operand tile)
#define STAGEB 36864      // A + B
#define GDYN (3 * STAGEB)

__global__ void __launch_bounds__(256, 2) k_gemm1_mma() {
    extern __shared__ __align__(16) char dsm[];
    int t = threadIdx.x, lane = t & 31, w = t >> 5;
    int wm = w & 1, wn = w >> 1;
    int m0 = blockIdx.y * 128;   // m over gridDim.y
    int n0 = blockIdx.x * 128;   // n over gridDim.x (4): A tile shared via L2
    uint32_t sbase = smem_u32(dsm);

    float acc[4][4][4];
#pragma unroll
    for (int i = 0; i < 4; i++)
#pragma unroll
        for (int j = 0; j < 4; j++)
#pragma unroll
            for (int q = 0; q < 4; q++) acc[i][j][q] = 0.f;

    // chunk c (0..11): pass = c/4 (0:AhiBhi 1:AloBhi 2:AhiBlo), kk = (c%4)*64
    auto issue_load = [&](int c) {
        int st = c % 3;
        int pass = c >> 2, kk = (c & 3) * 64;
        const __nv_bfloat16* Asrc = (pass == 1) ? g_Alo : g_Ahi;
        const __nv_bfloat16* Bsrc = (pass == 2) ? g_Blo : g_Bhi;
        uint32_t sa = sbase + st * STAGEB;
        uint32_t sb = sa + HALFSTAGE;
#pragma unroll
        for (int q = 0; q < 4; q++) {
            int idx = t + q * 256;
            int row = idx >> 3, gi = idx & 7;
            int gm = m0 + row;
            gm = gm < NN ? gm : NN - 1;
            cpa16(sa + row * 144 + gi * 16, Asrc + (size_t)gm * 256 + kk + gi * 8);
        }
#pragma unroll
        for (int q = 0; q < 4; q++) {
            int idx = t + q * 256;
            int row = idx >> 3, gi = idx & 7;
            cpa16(sb + row * 144 + gi * 16,
                  Bsrc + (size_t)(n0 + row) * 256 + kk + gi * 8);
        }
        asm volatile("cp.async.commit_group;" ::: "memory");
    };

    issue_load(0);
    issue_load(1);

    uint32_t aoff = (wm * 64 + (lane & 15)) * KS * 2 + (lane >> 4) * 16;
    uint32_t boff =
        ((wn * 32 + (lane & 7) + ((lane >> 4) & 1) * 8) * KS + ((lane >> 3) & 1) * 8) * 2;

    for (int c = 0; c < 12; c++) {
        if (c < 11) cpwait<1>(); else cpwait<0>();  // tail: wait for OWN group
        __syncthreads();
        if (c + 2 < 12) issue_load(c + 2);
        uint32_t sa = sbase + (c % 3) * STAGEB;
        uint32_t sb = sa + HALFSTAGE;

        uint32_t af[2][4][4], bf[2][2][4];
        auto ldfrag = [&](int ks, int s) {
#pragma unroll
            for (int mf = 0; mf < 4; mf++)
                ldm4(af[s][mf], sa + aoff + mf * (16 * KS * 2) + ks * 32);
#pragma unroll
            for (int p = 0; p < 2; p++)
                ldm4(bf[s][p], sb + boff + p * (16 * KS * 2) + ks * 32);
        };
        ldfrag(0, 0);
#pragma unroll
        for (int ks = 0; ks < 4; ks++) {
            int cur = ks & 1;
            if (ks < 3) ldfrag(ks + 1, cur ^ 1);
#pragma unroll
            for (int mf = 0; mf < 4; mf++)
#pragma unroll
                for (int nf = 0; nf < 4; nf++) {
                    int p = nf >> 1, hi = (nf & 1) * 2;
                    mma16816(acc[mf][nf], af[cur][mf], bf[cur][p][hi],
                             bf[cur][p][hi + 1]);
                }
        }
    }

    // epilogue: add bias, write to g_xl1/g_xr1
#pragma unroll
    for (int mf = 0; mf < 4; mf++) {
        int row0 = m0 + wm * 64 + mf * 16 + (lane >> 2);
#pragma unroll
        for (int nf = 0; nf < 4; nf++) {
            int col = n0 + wn * 32 + nf * 8 + (lane & 3) * 2;
            float b0 = g_bcat1[col], b1 = g_bcat1[col + 1];
            float* base = (col < 256) ? g_xl1 : g_xr1;
            int cc = (col < 256) ? col : col - 256;
            if (row0 < NN) {
                float2 v = make_float2(acc[mf][nf][0] + b0, acc[mf][nf][1] + b1);
                *(float2*)(base + (size_t)row0 * 256 + cc) = v;
            }
            if (row0 + 8 < NN) {
                float2 v = make_float2(acc[mf][nf][2] + b0, acc[mf][nf][3] + b1);
                *(float2*)(base + (size_t)(row0 + 8) * 256 + cc) = v;
            }
        }
    }
}

// ---------------- layer-1 edge phase: warp per dst node, online softmax ----------------
// 2-edge interleave + 1-pair-ahead index prefetch.
__global__ void __launch_bounds__(256) k_edge1(const float* __restrict__ att1,
                                               const float* __restrict__ bias1) {
    int gw = (blockIdx.x * blockDim.x + threadIdx.x) >> 5;
    int lane = threadIdx.x & 31;
    if (gw >= NN) return;
    int d = gw;
    int cb = lane * 8;  // 8 channels per lane; head = lane>>3
    const float4* xrp = (const float4*)(g_xr1 + (size_t)d * 256 + cb);
    float4 xr0 = xrp[0], xr1v = xrp[1];
    const float4* ap = (const float4*)(att1 + cb);
    float4 at0 = ap[0], at1 = ap[1];
    int p0, p1;
    row_range(d, p0, p1);

    float m = -INFINITY, denom = 0.f;
    float4 acc0 = make_float4(0.f, 0.f, 0.f, 0.f), acc1 = acc0;

#define DOT8(r0, r1)                                                                \
    (lrelu((r0).x + xr0.x) * at0.x + lrelu((r0).y + xr0.y) * at0.y +                \
     lrelu((r0).z + xr0.z) * at0.z + lrelu((r0).w + xr0.w) * at0.w +                \
     lrelu((r1).x + xr1v.x) * at1.x + lrelu((r1).y + xr1v.y) * at1.y +              \
     lrelu((r1).z + xr1v.z) * at1.z + lrelu((r1).w + xr1v.w) * at1.w)

#define SMUP(pa, r0, r1)                                                            \
    do {                                                                            \
        if ((pa) > m) {                                                             \
            float sc_ = __expf(m - (pa));                                           \
            denom *= sc_;                                                           \
            acc0.x *= sc_; acc0.y *= sc_; acc0.z *= sc_; acc0.w *= sc_;             \
            acc1.x *= sc_; acc1.y *= sc_; acc1.z *= sc_; acc1.w *= sc_;             \
            m = (pa);                                                               \
        }                                                                           \
        float ee_ = __expf((pa)-m);                                                 \
        denom += ee_;                                                               \
        acc0.x += ee_ * (r0).x; acc0.y += ee_ * (r0).y;                             \
        acc0.z += ee_ * (r0).z; acc0.w += ee_ * (r0).w;                             \
        acc1.x += ee_ * (r1).x; acc1.y += ee_ * (r1).y;                             \
        acc1.z += ee_ * (r1).z; acc1.w += ee_ * (r1).w;                             \
    } while (0)

    int p = p0;
    float4 a0, a1, b0v, b1v;
    {
        int s = g_esrc[p];
        const float4* xs = (const float4*)(g_xl1 + (size_t)s * 256 + cb);
        a0 = xs[0]; a1 = xs[1];
    }
    if (p + 1 < p1) {
        int s = g_esrc[p + 1];
        const float4* xs = (const float4*)(g_xl1 + (size_t)s * 256 + cb);
        b0v = xs[0]; b1v = xs[1];
    }
    // indices for next pair, prefetched one iteration ahead
    int i2 = (p + 2 < p1) ? g_esrc[p + 2] : 0;
    int i3 = (p + 3 < p1) ? g_esrc[p + 3] : 0;
    while (p + 1 < p1) {
        const float4* x2 = (const float4*)(g_xl1 + (size_t)i2 * 256 + cb);
        const float4* x3 = (const float4*)(g_xl1 + (size_t)i3 * 256 + cb);
        float4 n0 = x2[0], n1 = x2[1], n2 = x3[0], n3 = x3[1];
        // prefetch indices two pairs ahead (overlaps the reduce chain below)
        i2 = (p + 4 < p1) ? g_esrc[p + 4] : 0;
        i3 = (p + 5 < p1) ? g_esrc[p + 5] : 0;

        float pa = DOT8(a0, a1);
        float pb = DOT8(b0v, b1v);
        pa += __shfl_xor_sync(0xffffffffu, pa, 1);
        pb += __shfl_xor_sync(0xffffffffu, pb, 1);
        pa += __shfl_xor_sync(0xffffffffu, pa, 2);
        pb += __shfl_xor_sync(0xffffffffu, pb, 2);
        pa += __shfl_xor_sync(0xffffffffu, pa, 4);
        pb += __shfl_xor_sync(0xffffffffu, pb, 4);

        SMUP(pa, a0, a1);
        SMUP(pb, b0v, b1v);

        a0 = n0; a1 = n1; b0v = n2; b1v = n3;
        p += 2;
    }
    if (p < p1) {
        float pa = DOT8(a0, a1);
        pa += __shfl_xor_sync(0xffffffffu, pa, 1);
        pa += __shfl_xor_sync(0xffffffffu, pa, 2);
        pa += __shfl_xor_sync(0xffffffffu, pa, 4);
        SMUP(pa, a0, a1);
    }
#undef DOT8
#undef SMUP

    float inv = 1.f / (denom + 1e-16f);
    const float4* bp = (const float4*)(bias1 + cb);
    float4 b0 = bp[0], b1 = bp[1];
    float vals[8];
    vals[0] = tanhf(acc0.x * inv + b0.x); vals[1] = tanhf(acc0.y * inv + b0.y);
    vals[2] = tanhf(acc0.z * inv + b0.z); vals[3] = tanhf(acc0.w * inv + b0.w);
    vals[4] = tanhf(acc1.x * inv + b1.x); vals[5] = tanhf(acc1.y * inv + b1.y);
    vals[6] = tanhf(acc1.z * inv + b1.z); vals[7] = tanhf(acc1.w * inv + b1.w);
    __nv_bfloat162 hi[4], lo[4];
#pragma unroll
    for (int i = 0; i < 4; i++) {
        __nv_bfloat16 h0 = __float2bfloat16(vals[2 * i]);
        __nv_bfloat16 h1 = __float2bfloat16(vals[2 * i + 1]);
        hi[i] = __halves2bfloat162(h0, h1);
        lo[i] = __halves2bfloat162(
            __float2bfloat16(vals[2 * i] - __bfloat162float(h0)),
            __float2bfloat16(vals[2 * i + 1] - __bfloat162float(h1)));
    }
    *(uint4*)(g_h1hi + (size_t)d * 256 + cb) = *(uint4*)hi;
    *(uint4*)(g_h1lo + (size_t)d * 256 + cb) = *(uint4*)lo;
}

// ---------------- GEMM2 (mma.sync bf16 hi/lo): h1[50000,256] @ W2[256,32] ----------------
#define G2_ATILE 18432            // 128 rows * 144B (stride 72 bf16)
#define G2_BTILE 16896            // 32 rows * 528B (stride 264 bf16)
#define G2_DYN (2 * 2 * G2_ATILE + 2 * G2_BTILE)  // 2 stages x (hi+lo) + Bhi + Blo

__global__ void __launch_bounds__(256) k_gemm2_mma() {
    extern __shared__ __align__(16) char dsm[];
    int t = threadIdx.x, lane = t & 31, w = t >> 5;
    int m0 = blockIdx.x * 128;
    uint32_t sbase = smem_u32(dsm);
    uint32_t aBase = sbase;                       // 2 stages x (Ahi|Alo)
    uint32_t bHi = sbase + 2 * 2 * G2_ATILE;
    uint32_t bLo = bHi + G2_BTILE;

#pragma unroll
    for (int q = 0; q < 4; q++) {
        int idx = t + q * 256;
        int row = idx >> 5, gi = idx & 31;
        cpa16(bHi + row * 528 + gi * 16, g_W2hi + row * 256 + gi * 8);
        cpa16(bLo + row * 528 + gi * 16, g_W2lo + row * 256 + gi * 8);
    }
    asm volatile("cp.async.commit_group;" ::: "memory");

    auto loadA = [&](int c) {
        uint32_t sa = aBase + (c & 1) * 2 * G2_ATILE;
#pragma unroll
        for (int q = 0; q < 4; q++) {
            int idx = t + q * 256;
            int row = idx >> 3, gi = idx & 7;
            int gm = m0 + row;
            gm = gm < NN ? gm : NN - 1;
            uint32_t off = row * 144 + gi * 16;
            size_t ga = (size_t)gm * 256 + c * 64 + gi * 8;
            cpa16(sa + off, g_h1hi + ga);
            cpa16(sa + G2_ATILE + off, g_h1lo + ga);
        }
        asm volatile("cp.async.commit_group;" ::: "memory");
    };
    loadA(0);
    loadA(1);

    float acc[4][4];
#pragma unroll
    for (int i = 0; i < 4; i++)
#pragma unroll
        for (int q = 0; q < 4; q++) acc[i][q] = 0.f;

    uint32_t arow = (w * 16 + (lane & 15)) * 144 + (lane >> 4) * 16;

    for (int c = 0; c < 4; c++) {
        if (c < 3) cpwait<1>(); else cpwait<0>();  // tail: wait for OWN group
        __syncthreads();
        uint32_t sa = aBase + (c & 1) * 2 * G2_ATILE;
#pragma unroll
        for (int ks = 0; ks < 4; ks++) {
            uint32_t ahi[4], alo[4];
            ldm4(ahi, sa + arow + ks * 32);
            ldm4(alo, sa + G2_ATILE + arow + ks * 32);
            int kg = c * 64 + ks * 16 + ((lane >> 3) & 1) * 8;
            uint32_t bhi[2][4], blo[2][4];
#pragma unroll
            for (int p = 0; p < 2; p++) {
                uint32_t nrow = p * 16 + (lane & 7) + ((lane >> 4) & 1) * 8;
                ldm4(bhi[p], bHi + nrow * 528 + kg * 2);
                ldm4(blo[p], bLo + nrow * 528 + kg * 2);
            }
#pragma unroll
            for (int nf = 0; nf < 4; nf++) {
                int p = nf >> 1, hi = (nf & 1) * 2;
                mma16816(acc[nf], ahi, bhi[p][hi], bhi[p][hi + 1]);
                mma16816(acc[nf], alo, bhi[p][hi], bhi[p][hi + 1]);
                mma16816(acc[nf], ahi, blo[p][hi], blo[p][hi + 1]);
            }
        }
        __syncthreads();
        if (c + 2 < 4) loadA(c + 2);
    }

    int row0 = m0 + w * 16 + (lane >> 2);
#pragma unroll
    for (int nf = 0; nf < 4; nf++) {
        int col = nf * 8 + (lane & 3) * 2;
        float b0 = g_bcat2[col], b1 = g_bcat2[col + 1];
        float* dst = (col < 16) ? g_xl2 : g_xr2;
        int cc = (col < 16) ? col : col - 16;
        if (row0 < NN) {
            float2 v = make_float2(acc[nf][0] + b0, acc[nf][1] + b1);
            *(float2*)(dst + (size_t)row0 * 16 + cc) = v;
        }
        if (row0 + 8 < NN) {
            float2 v = make_float2(acc[nf][2] + b0, acc[nf][3] + b1);
            *(float2*)(dst + (size_t)(row0 + 8) * 16 + cc) = v;
        }
    }
}

// ---------------- layer-2 edge phase + log_softmax: TWO nodes per warp ----------------
// lanes 0-15 -> node 2*warp, lanes 16-31 -> node 2*warp+1. Half-warp shfl masks.
// Index prefetch one edge ahead.
__global__ void __launch_bounds__(256) k_edge2(const float* __restrict__ att2,
                                               const float* __restrict__ bias2,
                                               float* __restrict__ outO,
                                               float* __restrict__ outLP) {
    int gw = (blockIdx.x * blockDim.x + threadIdx.x) >> 5;
    int lane = threadIdx.x & 31;
    int half = lane >> 4;
    int d = gw * 2 + half;
    if (d >= NN) return;
    unsigned hm = half ? 0xFFFF0000u : 0x0000FFFFu;
    int c = lane & 15;
    float xrv = g_xr2[(size_t)d * 16 + c];
    float av = att2[c];
    int p0, p1;
    row_range(d, p0, p1);

    float m = -INFINITY, denom = 0.f, acc = 0.f;

    int s = g_esrc[p0];
    float xv = g_xl2[(size_t)s * 16 + c];
    int i1 = (p0 + 1 < p1) ? g_esrc[p0 + 1] : 0;

    for (int p = p0; p < p1; p++) {
        float cx = xv;
        if (p + 1 < p1) {
            xv = g_xl2[(size_t)i1 * 16 + c];
            i1 = (p + 2 < p1) ? g_esrc[p + 2] : 0;
        }
        float v = cx + xrv;
        v = v > 0.f ? v : 0.2f * v;
        float pa = v * av;
        pa += __shfl_xor_sync(hm, pa, 1);
        pa += __shfl_xor_sync(hm, pa, 2);
        pa += __shfl_xor_sync(hm, pa, 4);
        pa += __shfl_xor_sync(hm, pa, 8);
        if (pa > m) {
            float sc = __expf(m - pa);
            denom *= sc;
            acc *= sc;
            m = pa;
        }
        float ee = __expf(pa - m);
        denom += ee;
        acc += ee * cx;
    }
    float o = acc / (denom + 1e-16f) + bias2[c];

    // log_softmax over the 16 channels (within each half)
    float mm = o;
    mm = fmaxf(mm, __shfl_xor_sync(hm, mm, 1));
    mm = fmaxf(mm, __shfl_xor_sync(hm, mm, 2));
    mm = fmaxf(mm, __shfl_xor_sync(hm, mm, 4));
    mm = fmaxf(mm, __shfl_xor_sync(hm, mm, 8));
    float se = __expf(o - mm);
    se += __shfl_xor_sync(hm, se, 1);
    se += __shfl_xor_sync(hm, se, 2);
    se += __shfl_xor_sync(hm, se, 4);
    se += __shfl_xor_sync(hm, se, 8);
    float lp = o - mm - logf(se);

    outO[(size_t)d * 16 + c] = o;
    if (outLP) outLP[(size_t)d * 16 + c] = lp;
}

// ---------------- launch ----------------
extern "C" void kernel_launch(void* const* d_in, const int* in_sizes, int n_in,
                              void* d_out, int out_size) {
    const float* x     = (const float*)d_in[0];
    const int*   ei    = (const int*)d_in[1];
    const float* Wl1   = (const float*)d_in[2];
    const float* bl1   = (const float*)d_in[3];
    const float* Wr1   = (const float*)d_in[4];
    const float* br1   = (const float*)d_in[5];
    const float* att1  = (const float*)d_in[6];
    const float* bias1 = (const float*)d_in[7];
    const float* Wl2   = (const float*)d_in[8];
    const float* bl2   = (const float*)d_in[9];
    const float* Wr2   = (const float*)d_in[10];
    const float* br2   = (const float*)d_in[11];
    const float* att2  = (const float*)d_in[12];
    const float* bias2 = (const float*)d_in[13];

    float* outO  = (float*)d_out;
    float* outLP = (out_size >= 2 * NN * OUTD) ? ((float*)d_out + NN * OUTD) : nullptr;

    cudaFuncSetAttribute(k_gemm1_mma, cudaFuncAttributeMaxDynamicSharedMemorySize,
                         GDYN);
    cudaFuncSetAttribute(k_gemm2_mma, cudaFuncAttributeMaxDynamicSharedMemorySize,
                         G2_DYN);

    // Order keeps k_gemm1_mma at launch index 3 (the profiled slot):
    k_init<<<(NN * 64 + 255) / 256, 256>>>(x, ei, Wl1, Wr1, bl1, br1, Wl2, bl2, Wr2,
                                           br2);
    k_scan1<<<SCAN_BLOCKS, 1024>>>();
    k_scatter<<<(E2 + 255) / 256, 256>>>(ei);
    dim3 g1(4, MTILES);
    k_gemm1_mma<<<g1, 256, GDYN>>>();

    k_edge1<<<(NN + 7) / 8, 256>>>(att1, bias1);
    k_gemm2_mma<<<MTILES, 256, G2_DYN>>>();
    // two nodes per warp: 25000 warps
    k_edge2<<<(25000 * 32 + 255) / 256, 256>>>(att2, bias2, outO, outLP);
}

// round 17
// speedup vs baseline: 1.0096x; 1.0096x over previous
#include <cuda_runtime.h>
#include <cuda_bf16.h>
#include <math.h>
#include <stdint.h>

#define NN 50000
#define EE 400000
#define E2 (EE + NN)
#define OUTD 16
#define MTILES 391  // ceil(50000/128)

// ---------------- scratch (device globals; no allocs allowed) ----------------
__device__ __align__(16) float g_xl1[NN * 256];
__device__ __align__(16) float g_xr1[NN * 256];
__device__ __align__(16) float g_xl2[NN * OUTD];
__device__ __align__(16) float g_xr2[NN * OUTD];
__device__ int g_esrc[E2];
__device__ int g_counts[NN];   // zero-initialized; re-zeroed by k_scan1 each call
__device__ int g_fill[NN];     // zero-initialized; re-zeroed by k_scan1 each call
__device__ int g_rowptr[NN + 1];
__device__ int g_bsum[64];
__device__ int g_boff[64];
__device__ int g_scanctr;      // zero-init; self-resetting
__device__ __align__(16) float g_bcat1[512];
__device__ __align__(16) float g_bcat2[32];
// bf16 hi/lo split operands for tensor-core GEMMs
__device__ __align__(16) __nv_bfloat16 g_Ahi[NN * 256];
__device__ __align__(16) __nv_bfloat16 g_Alo[NN * 256];
__device__ __align__(16) __nv_bfloat16 g_Bhi[512 * 256];
__device__ __align__(16) __nv_bfloat16 g_Blo[512 * 256];
__device__ __align__(16) __nv_bfloat16 g_h1hi[NN * 256];
__device__ __align__(16) __nv_bfloat16 g_h1lo[NN * 256];
__device__ __align__(16) __nv_bfloat16 g_W2hi[32 * 256];
__device__ __align__(16) __nv_bfloat16 g_W2lo[32 * 256];

__device__ __forceinline__ float lrelu(float v) { return v > 0.f ? v : 0.2f * v; }

// ---------------- PTX helpers (arch-portable: ldmatrix + mma.sync) ----------------
__device__ __forceinline__ uint32_t smem_u32(const void* p) {
    uint32_t a;
    asm("{ .reg .u64 t; cvta.to.shared.u64 t, %1; cvt.u32.u64 %0, t; }"
        : "=r"(a) : "l"(p));
    return a;
}
__device__ __forceinline__ void cpa16(uint32_t dst, const void* src) {
    asm volatile("cp.async.cg.shared.global [%0], [%1], 16;" ::"r"(dst), "l"(src)
                 : "memory");
}
template <int N>
__device__ __forceinline__ void cpwait() {
    asm volatile("cp.async.wait_group %0;" ::"n"(N) : "memory");
}
__device__ __forceinline__ void ldm4(uint32_t* r, uint32_t addr) {
    asm volatile("ldmatrix.sync.aligned.m8n8.x4.shared.b16 {%0,%1,%2,%3}, [%4];"
                 : "=r"(r[0]), "=r"(r[1]), "=r"(r[2]), "=r"(r[3])
                 : "r"(addr));
}
__device__ __forceinline__ void mma16816(float* c, const uint32_t* a, uint32_t b0,
                                         uint32_t b1) {
    asm volatile(
        "mma.sync.aligned.m16n8k16.row.col.f32.bf16.bf16.f32 "
        "{%0,%1,%2,%3}, {%4,%5,%6,%7}, {%8,%9}, {%0,%1,%2,%3};"
        : "+f"(c[0]), "+f"(c[1]), "+f"(c[2]), "+f"(c[3])
        : "r"(a[0]), "r"(a[1]), "r"(a[2]), "r"(a[3]), "r"(b0), "r"(b1));
}

// ---------------- fused init: conv_x + conv_w + prep(W2/biases) + hist ----------------
__global__ void k_init(const float* __restrict__ X,
                       const int* __restrict__ ei,
                       const float* __restrict__ Wl1, const float* __restrict__ Wr1,
                       const float* __restrict__ bl1, const float* __restrict__ br1,
                       const float* __restrict__ Wl2, const float* __restrict__ bl2,
                       const float* __restrict__ Wr2, const float* __restrict__ br2) {
    int i = blockIdx.x * blockDim.x + threadIdx.x;
    if (i < NN * 64) {
        float4 v = ((const float4*)X)[i];
        __nv_bfloat16 h0 = __float2bfloat16(v.x);
        __nv_bfloat16 h1 = __float2bfloat16(v.y);
        __nv_bfloat16 h2 = __float2bfloat16(v.z);
        __nv_bfloat16 h3 = __float2bfloat16(v.w);
        __nv_bfloat16 l0 = __float2bfloat16(v.x - __bfloat162float(h0));
        __nv_bfloat16 l1 = __float2bfloat16(v.y - __bfloat162float(h1));
        __nv_bfloat16 l2 = __float2bfloat16(v.z - __bfloat162float(h2));
        __nv_bfloat16 l3 = __float2bfloat16(v.w - __bfloat162float(h3));
        *(__nv_bfloat162*)(g_Ahi + (size_t)i * 4)     = __halves2bfloat162(h0, h1);
        *(__nv_bfloat162*)(g_Ahi + (size_t)i * 4 + 2) = __halves2bfloat162(h2, h3);
        *(__nv_bfloat162*)(g_Alo + (size_t)i * 4)     = __halves2bfloat162(l0, l1);
        *(__nv_bfloat162*)(g_Alo + (size_t)i * 4 + 2) = __halves2bfloat162(l2, l3);
    }
    if (i < 512 * 256) {
        int n = i >> 8, k = i & 255;
        float v = (n < 256) ? Wl1[k * 256 + n] : Wr1[k * 256 + (n - 256)];
        __nv_bfloat16 h = __float2bfloat16(v);
        g_Bhi[n * 256 + k] = h;
        g_Blo[n * 256 + k] = __float2bfloat16(v - __bfloat162float(h));
    }
    if (i < 32 * 256) {
        int n = i >> 8, k = i & 255;
        float v = (n < 16) ? Wl2[k * 16 + n] : Wr2[k * 16 + (n - 16)];
        __nv_bfloat16 h = __float2bfloat16(v);
        g_W2hi[n * 256 + k] = h;
        g_W2lo[n * 256 + k] = __float2bfloat16(v - __bfloat162float(h));
    }
    if (i < 512) g_bcat1[i] = (i < 256) ? bl1[i] : br1[i - 256];
    if (i < 32) g_bcat2[i] = (i < 16) ? bl2[i] : br2[i - 16];
    if (i < E2) {
        int dd = (i < EE) ? ei[EE + i] : (i - EE);
        atomicAdd(&g_counts[dd], 1);
    }
}

#define SCAN_BLOCKS 49

// scan1 + fused scan2 (last-block-done) + counter re-zeroing for next replay
__global__ void k_scan1() {
    __shared__ int wsum[32];
    int tid = threadIdx.x;
    int lane = tid & 31, w = tid >> 5;
    int i = blockIdx.x * 1024 + tid;
    int v = (i < NN) ? g_counts[i] : 0;
    int x = v;
#pragma unroll
    for (int st = 1; st < 32; st <<= 1) {
        int y = __shfl_up_sync(0xffffffffu, x, st);
        if (lane >= st) x += y;
    }
    if (lane == 31) wsum[w] = x;
    __syncthreads();
    if (w == 0) {
        int s = wsum[lane];
#pragma unroll
        for (int st = 1; st < 32; st <<= 1) {
            int y = __shfl_up_sync(0xffffffffu, s, st);
            if (lane >= st) s += y;
        }
        wsum[lane] = s;
    }
    __syncthreads();
    int off = (w > 0) ? wsum[w - 1] : 0;
    int incl = x + off;
    if (i < NN) {
        g_rowptr[i] = incl - v;
        g_counts[i] = 0;
        g_fill[i] = 0;
    }
    if (tid == 1023) g_bsum[blockIdx.x] = incl;
    __syncthreads();
    if (tid == 0) {
        __threadfence();
        int prev = atomicAdd(&g_scanctr, 1);
        if (prev == SCAN_BLOCKS - 1) {
            g_scanctr = 0;
            __threadfence();
            int acc = 0;
            for (int b = 0; b < SCAN_BLOCKS; b++) { g_boff[b] = acc; acc += g_bsum[b]; }
            g_rowptr[NN] = acc;
        }
    }
}

__global__ void k_scan3() {
    int i = blockIdx.x * 1024 + threadIdx.x;
    int off = g_boff[blockIdx.x];
    if (i < NN && blockIdx.x > 0) g_rowptr[i] += off;
}

// ---------------- GEMM1 (mma.sync bf16 hi/lo) + fused scatter ----------------
// blockIdx.x < 4: 128x128 GEMM tile (R12 config, proven best: 2 CTAs/SM).
// blockIdx.x == 4: CSR scatter (391 blocks x 256 threads) overlapped with GEMM.
#define KS 72             // bf16 elems per smem row (144B: 16B-aligned, conflict-free)
#define HALFSTAGE 18432   // 128*72*2 bytes (one operand tile)
#define STAGEB 36864      // A + B
#define GDYN (3 * STAGEB)

__global__ void __launch_bounds__(256, 2) k_gemm1_mma(const int* __restrict__ ei) {
    extern __shared__ __align__(16) char dsm[];
    if (blockIdx.x == 4) {
        // fused scatter: rowptr is final (scan3 ran); overlaps with GEMM tiles
        for (int i = blockIdx.y * 256 + threadIdx.x; i < E2; i += MTILES * 256) {
            int s  = (i < EE) ? ei[i]      : (i - EE);
            int dd = (i < EE) ? ei[EE + i] : (i - EE);
            int pos = g_rowptr[dd] + atomicAdd(&g_fill[dd], 1);
            g_esrc[pos] = s;
        }
        return;
    }
    int t = threadIdx.x, lane = t & 31, w = t >> 5;
    int wm = w & 1, wn = w >> 1;
    int m0 = blockIdx.y * 128;   // m over gridDim.y
    int n0 = blockIdx.x * 128;   // n over gridDim.x (4): A tile shared via L2
    uint32_t sbase = smem_u32(dsm);

    float acc[4][4][4];
#pragma unroll
    for (int i = 0; i < 4; i++)
#pragma unroll
        for (int j = 0; j < 4; j++)
#pragma unroll
            for (int q = 0; q < 4; q++) acc[i][j][q] = 0.f;

    // chunk c (0..11): pass = c/4 (0:AhiBhi 1:AloBhi 2:AhiBlo), kk = (c%4)*64
    auto issue_load = [&](int c) {
        int st = c % 3;
        int pass = c >> 2, kk = (c & 3) * 64;
        const __nv_bfloat16* Asrc = (pass == 1) ? g_Alo : g_Ahi;
        const __nv_bfloat16* Bsrc = (pass == 2) ? g_Blo : g_Bhi;
        uint32_t sa = sbase + st * STAGEB;
        uint32_t sb = sa + HALFSTAGE;
#pragma unroll
        for (int q = 0; q < 4; q++) {
            int idx = t + q * 256;
            int row = idx >> 3, gi = idx & 7;
            int gm = m0 + row;
            gm = gm < NN ? gm : NN - 1;
            cpa16(sa + row * 144 + gi * 16, Asrc + (size_t)gm * 256 + kk + gi * 8);
        }
#pragma unroll
        for (int q = 0; q < 4; q++) {
            int idx = t + q * 256;
            int row = idx >> 3, gi = idx & 7;
            cpa16(sb + row * 144 + gi * 16,
                  Bsrc + (size_t)(n0 + row) * 256 + kk + gi * 8);
        }
        asm volatile("cp.async.commit_group;" ::: "memory");
    };

    issue_load(0);
    issue_load(1);

    uint32_t aoff = (wm * 64 + (lane & 15)) * KS * 2 + (lane >> 4) * 16;
    uint32_t boff =
        ((wn * 32 + (lane & 7) + ((lane >> 4) & 1) * 8) * KS + ((lane >> 3) & 1) * 8) * 2;

    for (int c = 0; c < 12; c++) {
        if (c < 11) cpwait<1>(); else cpwait<0>();  // tail: wait for OWN group
        __syncthreads();
        if (c + 2 < 12) issue_load(c + 2);
        uint32_t sa = sbase + (c % 3) * STAGEB;
        uint32_t sb = sa + HALFSTAGE;

        uint32_t af[2][4][4], bf[2][2][4];
        auto ldfrag = [&](int ks, int s) {
#pragma unroll
            for (int mf = 0; mf < 4; mf++)
                ldm4(af[s][mf], sa + aoff + mf * (16 * KS * 2) + ks * 32);
#pragma unroll
            for (int p = 0; p < 2; p++)
                ldm4(bf[s][p], sb + boff + p * (16 * KS * 2) + ks * 32);
        };
        ldfrag(0, 0);
#pragma unroll
        for (int ks = 0; ks < 4; ks++) {
            int cur = ks & 1;
            if (ks < 3) ldfrag(ks + 1, cur ^ 1);
#pragma unroll
            for (int mf = 0; mf < 4; mf++)
#pragma unroll
                for (int nf = 0; nf < 4; nf++) {
                    int p = nf >> 1, hi = (nf & 1) * 2;
                    mma16816(acc[mf][nf], af[cur][mf], bf[cur][p][hi],
                             bf[cur][p][hi + 1]);
                }
        }
    }

    // epilogue: add bias, write to g_xl1/g_xr1
#pragma unroll
    for (int mf = 0; mf < 4; mf++) {
        int row0 = m0 + wm * 64 + mf * 16 + (lane >> 2);
#pragma unroll
        for (int nf = 0; nf < 4; nf++) {
            int col = n0 + wn * 32 + nf * 8 + (lane & 3) * 2;
            float b0 = g_bcat1[col], b1 = g_bcat1[col + 1];
            float* base = (col < 256) ? g_xl1 : g_xr1;
            int cc = (col < 256) ? col : col - 256;
            if (row0 < NN) {
                float2 v = make_float2(acc[mf][nf][0] + b0, acc[mf][nf][1] + b1);
                *(float2*)(base + (size_t)row0 * 256 + cc) = v;
            }
            if (row0 + 8 < NN) {
                float2 v = make_float2(acc[mf][nf][2] + b0, acc[mf][nf][3] + b1);
                *(float2*)(base + (size_t)(row0 + 8) * 256 + cc) = v;
            }
        }
    }
}

// ---------------- layer-1 edge phase: warp per dst node, online softmax, 2-edge interleave ----------------
__global__ void __launch_bounds__(256) k_edge1(const float* __restrict__ att1,
                                               const float* __restrict__ bias1) {
    int gw = (blockIdx.x * blockDim.x + threadIdx.x) >> 5;
    int lane = threadIdx.x & 31;
    if (gw >= NN) return;
    int d = gw;
    int cb = lane * 8;  // 8 channels per lane; head = lane>>3
    const float4* xrp = (const float4*)(g_xr1 + (size_t)d * 256 + cb);
    float4 xr0 = xrp[0], xr1v = xrp[1];
    const float4* ap = (const float4*)(att1 + cb);
    float4 at0 = ap[0], at1 = ap[1];
    int p0 = g_rowptr[d], p1 = g_rowptr[d + 1];

    float m = -INFINITY, denom = 0.f;
    float4 acc0 = make_float4(0.f, 0.f, 0.f, 0.f), acc1 = acc0;

#define DOT8(r0, r1)                                                                \
    (lrelu((r0).x + xr0.x) * at0.x + lrelu((r0).y + xr0.y) * at0.y +                \
     lrelu((r0).z + xr0.z) * at0.z + lrelu((r0).w + xr0.w) * at0.w +                \
     lrelu((r1).x + xr1v.x) * at1.x + lrelu((r1).y + xr1v.y) * at1.y +              \
     lrelu((r1).z + xr1v.z) * at1.z + lrelu((r1).w + xr1v.w) * at1.w)

#define SMUP(pa, r0, r1)                                                            \
    do {                                                                            \
        if ((pa) > m) {                                                             \
            float sc_ = __expf(m - (pa));                                           \
            denom *= sc_;                                                           \
            acc0.x *= sc_; acc0.y *= sc_; acc0.z *= sc_; acc0.w *= sc_;             \
            acc1.x *= sc_; acc1.y *= sc_; acc1.z *= sc_; acc1.w *= sc_;             \
            m = (pa);                                                               \
        }                                                                           \
        float ee_ = __expf((pa)-m);                                                 \
        denom += ee_;                                                               \
        acc0.x += ee_ * (r0).x; acc0.y += ee_ * (r0).y;                             \
        acc0.z += ee_ * (r0).z; acc0.w += ee_ * (r0).w;                             \
        acc1.x += ee_ * (r1).x; acc1.y += ee_ * (r1).y;                             \
        acc1.z += ee_ * (r1).z; acc1.w += ee_ * (r1).w;                             \
    } while (0)

    int p = p0;
    float4 a0, a1, b0v, b1v;
    {
        int s = g_esrc[p];
        const float4* xs = (const float4*)(g_xl1 + (size_t)s * 256 + cb);
        a0 = xs[0]; a1 = xs[1];
    }
    if (p + 1 < p1) {
        int s = g_esrc[p + 1];
        const float4* xs = (const float4*)(g_xl1 + (size_t)s * 256 + cb);
        b0v = xs[0]; b1v = xs[1];
    }
    while (p + 1 < p1) {
        int s2 = g_esrc[(p + 2 < p1) ? p + 2 : p];
        int s3 = g_esrc[(p + 3 < p1) ? p + 3 : p];
        const float4* x2 = (const float4*)(g_xl1 + (size_t)s2 * 256 + cb);
        const float4* x3 = (const float4*)(g_xl1 + (size_t)s3 * 256 + cb);
        float4 n0 = x2[0], n1 = x2[1], n2 = x3[0], n3 = x3[1];

        float pa = DOT8(a0, a1);
        float pb = DOT8(b0v, b1v);
        pa += __shfl_xor_sync(0xffffffffu, pa, 1);
        pb += __shfl_xor_sync(0xffffffffu, pb, 1);
        pa += __shfl_xor_sync(0xffffffffu, pa, 2);
        pb += __shfl_xor_sync(0xffffffffu, pb, 2);
        pa += __shfl_xor_sync(0xffffffffu, pa, 4);
        pb += __shfl_xor_sync(0xffffffffu, pb, 4);

        SMUP(pa, a0, a1);
        SMUP(pb, b0v, b1v);

        a0 = n0; a1 = n1; b0v = n2; b1v = n3;
        p += 2;
    }
    if (p < p1) {
        float pa = DOT8(a0, a1);
        pa += __shfl_xor_sync(0xffffffffu, pa, 1);
        pa += __shfl_xor_sync(0xffffffffu, pa, 2);
        pa += __shfl_xor_sync(0xffffffffu, pa, 4);
        SMUP(pa, a0, a1);
    }
#undef DOT8
#undef SMUP

    float inv = 1.f / (denom + 1e-16f);
    const float4* bp = (const float4*)(bias1 + cb);
    float4 b0 = bp[0], b1 = bp[1];
    float vals[8];
    vals[0] = tanhf(acc0.x * inv + b0.x); vals[1] = tanhf(acc0.y * inv + b0.y);
    vals[2] = tanhf(acc0.z * inv + b0.z); vals[3] = tanhf(acc0.w * inv + b0.w);
    vals[4] = tanhf(acc1.x * inv + b1.x); vals[5] = tanhf(acc1.y * inv + b1.y);
    vals[6] = tanhf(acc1.z * inv + b1.z); vals[7] = tanhf(acc1.w * inv + b1.w);
    __nv_bfloat162 hi[4], lo[4];
#pragma unroll
    for (int i = 0; i < 4; i++) {
        __nv_bfloat16 h0 = __float2bfloat16(vals[2 * i]);
        __nv_bfloat16 h1 = __float2bfloat16(vals[2 * i + 1]);
        hi[i] = __halves2bfloat162(h0, h1);
        lo[i] = __halves2bfloat162(
            __float2bfloat16(vals[2 * i] - __bfloat162float(h0)),
            __float2bfloat16(vals[2 * i + 1] - __bfloat162float(h1)));
    }
    *(uint4*)(g_h1hi + (size_t)d * 256 + cb) = *(uint4*)hi;
    *(uint4*)(g_h1lo + (size_t)d * 256 + cb) = *(uint4*)lo;
}

// ---------------- GEMM2 (mma.sync bf16 hi/lo): h1[50000,256] @ W2[256,32] ----------------
#define G2_ATILE 18432            // 128 rows * 144B (stride 72 bf16)
#define G2_BTILE 16896            // 32 rows * 528B (stride 264 bf16)
#define G2_DYN (2 * 2 * G2_ATILE + 2 * G2_BTILE)  // 2 stages x (hi+lo) + Bhi + Blo

__global__ void __launch_bounds__(256) k_gemm2_mma() {
    extern __shared__ __align__(16) char dsm[];
    int t = threadIdx.x, lane = t & 31, w = t >> 5;
    int m0 = blockIdx.x * 128;
    uint32_t sbase = smem_u32(dsm);
    uint32_t aBase = sbase;                       // 2 stages x (Ahi|Alo)
    uint32_t bHi = sbase + 2 * 2 * G2_ATILE;
    uint32_t bLo = bHi + G2_BTILE;

#pragma unroll
    for (int q = 0; q < 4; q++) {
        int idx = t + q * 256;
        int row = idx >> 5, gi = idx & 31;
        cpa16(bHi + row * 528 + gi * 16, g_W2hi + row * 256 + gi * 8);
        cpa16(bLo + row * 528 + gi * 16, g_W2lo + row * 256 + gi * 8);
    }
    asm volatile("cp.async.commit_group;" ::: "memory");

    auto loadA = [&](int c) {
        uint32_t sa = aBase + (c & 1) * 2 * G2_ATILE;
#pragma unroll
        for (int q = 0; q < 4; q++) {
            int idx = t + q * 256;
            int row = idx >> 3, gi = idx & 7;
            int gm = m0 + row;
            gm = gm < NN ? gm : NN - 1;
            uint32_t off = row * 144 + gi * 16;
            size_t ga = (size_t)gm * 256 + c * 64 + gi * 8;
            cpa16(sa + off, g_h1hi + ga);
            cpa16(sa + G2_ATILE + off, g_h1lo + ga);
        }
        asm volatile("cp.async.commit_group;" ::: "memory");
    };
    loadA(0);
    loadA(1);

    float acc[4][4];
#pragma unroll
    for (int i = 0; i < 4; i++)
#pragma unroll
        for (int q = 0; q < 4; q++) acc[i][q] = 0.f;

    uint32_t arow = (w * 16 + (lane & 15)) * 144 + (lane >> 4) * 16;

    for (int c = 0; c < 4; c++) {
        if (c < 3) cpwait<1>(); else cpwait<0>();  // tail: wait for OWN group
        __syncthreads();
        uint32_t sa = aBase + (c & 1) * 2 * G2_ATILE;
#pragma unroll
        for (int ks = 0; ks < 4; ks++) {
            uint32_t ahi[4], alo[4];
            ldm4(ahi, sa + arow + ks * 32);
            ldm4(alo, sa + G2_ATILE + arow + ks * 32);
            int kg = c * 64 + ks * 16 + ((lane >> 3) & 1) * 8;
            uint32_t bhi[2][4], blo[2][4];
#pragma unroll
            for (int p = 0; p < 2; p++) {
                uint32_t nrow = p * 16 + (lane & 7) + ((lane >> 4) & 1) * 8;
                ldm4(bhi[p], bHi + nrow * 528 + kg * 2);
                ldm4(blo[p], bLo + nrow * 528 + kg * 2);
            }
#pragma unroll
            for (int nf = 0; nf < 4; nf++) {
                int p = nf >> 1, hi = (nf & 1) * 2;
                mma16816(acc[nf], ahi, bhi[p][hi], bhi[p][hi + 1]);
                mma16816(acc[nf], alo, bhi[p][hi], bhi[p][hi + 1]);
                mma16816(acc[nf], ahi, blo[p][hi], blo[p][hi + 1]);
            }
        }
        __syncthreads();
        if (c + 2 < 4) loadA(c + 2);
    }

    int row0 = m0 + w * 16 + (lane >> 2);
#pragma unroll
    for (int nf = 0; nf < 4; nf++) {
        int col = nf * 8 + (lane & 3) * 2;
        float b0 = g_bcat2[col], b1 = g_bcat2[col + 1];
        float* dst = (col < 16) ? g_xl2 : g_xr2;
        int cc = (col < 16) ? col : col - 16;
        if (row0 < NN) {
            float2 v = make_float2(acc[nf][0] + b0, acc[nf][1] + b1);
            *(float2*)(dst + (size_t)row0 * 16 + cc) = v;
        }
        if (row0 + 8 < NN) {
            float2 v = make_float2(acc[nf][2] + b0, acc[nf][3] + b1);
            *(float2*)(dst + (size_t)(row0 + 8) * 16 + cc) = v;
        }
    }
}

// ---------------- layer-2 edge phase + log_softmax: TWO nodes per warp ----------------
// lanes 0-15 -> node 2*warp, lanes 16-31 -> node 2*warp+1. Half-warp shfl masks.
__global__ void __launch_bounds__(256) k_edge2(const float* __restrict__ att2,
                                               const float* __restrict__ bias2,
                                               float* __restrict__ outO,
                                               float* __restrict__ outLP) {
    int gw = (blockIdx.x * blockDim.x + threadIdx.x) >> 5;
    int lane = threadIdx.x & 31;
    int half = lane >> 4;
    int d = gw * 2 + half;
    if (d >= NN) return;
    unsigned hm = half ? 0xFFFF0000u : 0x0000FFFFu;
    int c = lane & 15;
    float xrv = g_xr2[(size_t)d * 16 + c];
    float av = att2[c];
    int p0 = g_rowptr[d], p1 = g_rowptr[d + 1];

    float m = -INFINITY, denom = 0.f, acc = 0.f;

    int s = g_esrc[p0];
    float xv = g_xl2[(size_t)s * 16 + c];

    for (int p = p0; p < p1; p++) {
        float cx = xv;
        if (p + 1 < p1) {
            int s2 = g_esrc[p + 1];
            xv = g_xl2[(size_t)s2 * 16 + c];
        }
        float v = cx + xrv;
        v = v > 0.f ? v : 0.2f * v;
        float pa = v * av;
        pa += __shfl_xor_sync(hm, pa, 1);
        pa += __shfl_xor_sync(hm, pa, 2);
        pa += __shfl_xor_sync(hm, pa, 4);
        pa += __shfl_xor_sync(hm, pa, 8);
        if (pa > m) {
            float sc = __expf(m - pa);
            denom *= sc;
            acc *= sc;
            m = pa;
        }
        float ee = __expf(pa - m);
        denom += ee;
        acc += ee * cx;
    }
    float o = acc / (denom + 1e-16f) + bias2[c];

    // log_softmax over the 16 channels (within each half)
    float mm = o;
    mm = fmaxf(mm, __shfl_xor_sync(hm, mm, 1));
    mm = fmaxf(mm, __shfl_xor_sync(hm, mm, 2));
    mm = fmaxf(mm, __shfl_xor_sync(hm, mm, 4));
    mm = fmaxf(mm, __shfl_xor_sync(hm, mm, 8));
    float se = __expf(o - mm);
    se += __shfl_xor_sync(hm, se, 1);
    se += __shfl_xor_sync(hm, se, 2);
    se += __shfl_xor_sync(hm, se, 4);
    se += __shfl_xor_sync(hm, se, 8);
    float lp = o - mm - logf(se);

    outO[(size_t)d * 16 + c] = o;
    if (outLP) outLP[(size_t)d * 16 + c] = lp;
}

// ---------------- launch ----------------
extern "C" void kernel_launch(void* const* d_in, const int* in_sizes, int n_in,
                              void* d_out, int out_size) {
    const float* x     = (const float*)d_in[0];
    const int*   ei    = (const int*)d_in[1];
    const float* Wl1   = (const float*)d_in[2];
    const float* bl1   = (const float*)d_in[3];
    const float* Wr1   = (const float*)d_in[4];
    const float* br1   = (const float*)d_in[5];
    const float* att1  = (const float*)d_in[6];
    const float* bias1 = (const float*)d_in[7];
    const float* Wl2   = (const float*)d_in[8];
    const float* bl2   = (const float*)d_in[9];
    const float* Wr2   = (const float*)d_in[10];
    const float* br2   = (const float*)d_in[11];
    const float* att2  = (const float*)d_in[12];
    const float* bias2 = (const float*)d_in[13];

    float* outO  = (float*)d_out;
    float* outLP = (out_size >= 2 * NN * OUTD) ? ((float*)d_out + NN * OUTD) : nullptr;

    cudaFuncSetAttribute(k_gemm1_mma, cudaFuncAttributeMaxDynamicSharedMemorySize,
                         GDYN);
    cudaFuncSetAttribute(k_gemm2_mma, cudaFuncAttributeMaxDynamicSharedMemorySize,
                         G2_DYN);

    // Order keeps k_gemm1_mma at launch index 3 (the profiled slot):
    k_init<<<(NN * 64 + 255) / 256, 256>>>(x, ei, Wl1, Wr1, bl1, br1, Wl2, bl2, Wr2,
                                           br2);
    k_scan1<<<SCAN_BLOCKS, 1024>>>();
    k_scan3<<<SCAN_BLOCKS, 1024>>>();
    dim3 g1(5, MTILES);  // x==4 column runs the fused scatter
    k_gemm1_mma<<<g1, 256, GDYN>>>(ei);

    k_edge1<<<(NN + 7) / 8, 256>>>(att1, bias1);
    k_gemm2_mma<<<MTILES, 256, G2_DYN>>>();
    // two nodes per warp: 25000 warps
    k_edge2<<<(25000 * 32 + 255) / 256, 256>>>(att2, bias2, outO, outLP);
}